// round 12
// baseline (speedup 1.0000x reference)
#include <cuda_runtime.h>
#include <cuda_fp16.h>
#include <math.h>
#include <stdint.h>

// Problem constants
#define RES    8192
#define TSTEPS 1024
#define SDIM   128

// Main kernel config
#define NBLK    128     // persistent blocks, 1 per SM
#define RPB     64      // rows of W_res per block
#define THREADS 512     // 16 warps, 4 rows per warp (128 regs/thread budget)
#define RPW     4       // rows per warp
#define CPIN    1536    // cols pinned in SMEM  (64*1536*2B = 192 KB/SM, 24 MiB chip)
#define CREG    1024    // cols pinned in REGISTERS (64 regs/lane, 16 MiB chip)
#define CSTR    (CPIN + CREG)          // 2560: streamed cols start
#define NSTRIT  ((RES - CSTR) / 128)   // 44 streamed 128-col tiles (88 MiB chip)
#define NPIN    (CPIN / 128)           // 12 SMEM-pinned tiles

// Scratch (static device globals -- no allocations allowed)
__device__ __half  g_Wh[(size_t)RES * RES];            // 128 MiB fp16 weights
__device__ float   g_inproj[(size_t)TSTEPS * RES];     // 32 MiB
__device__ float   g_rbuf[2][RES];                     // double-buffered state
__device__ unsigned g_count;                           // barrier arrivals
__device__ unsigned g_gen;                             // barrier generation

// cp.async 16B global->shared via L2 (bypasses L1: coherent with other SMs)
__device__ __forceinline__ void cp16(float* smem_dst, const float* gmem_src) {
    uint32_t s = (uint32_t)__cvta_generic_to_shared(smem_dst);
    asm volatile("cp.async.cg.shared.global [%0], [%1], 16;" :: "r"(s), "l"(gmem_src));
}

// ---------------------------------------------------------------------------
// fp32 -> fp16 weight conversion
// ---------------------------------------------------------------------------
__global__ void convert_kernel(const float* __restrict__ W) {
    size_t i = ((size_t)blockIdx.x * blockDim.x + threadIdx.x) * 4;
    float4 v = *(const float4*)(W + i);
    __half2* o = (__half2*)(g_Wh + i);
    o[0] = __floats2half2_rn(v.x, v.y);
    o[1] = __floats2half2_rn(v.z, v.w);
}

// ---------------------------------------------------------------------------
// in_proj[t][j] = b[j] + sum_k in_seq[t][k] * W_in[j][k]
// ---------------------------------------------------------------------------
__global__ void inproj_kernel(const float* __restrict__ in_seq,
                              const float* __restrict__ W_in,
                              const float* __restrict__ b_res) {
    extern __shared__ float sm[];
    float* Ws = sm;                 // [128][129] padded
    float* Us = sm + 128 * 129;     // [64][128]
    const int jb  = blockIdx.x * 128;
    const int tb  = blockIdx.y * 64;
    const int tid = threadIdx.x;

    for (int idx = tid; idx < 128 * 128; idx += 128) {
        int r = idx >> 7, k = idx & 127;
        Ws[r * 129 + k] = W_in[(size_t)(jb + r) * SDIM + k];
    }
    for (int idx = tid; idx < 64 * 128; idx += 128) {
        int t = idx >> 7, k = idx & 127;
        Us[idx] = in_seq[(size_t)(tb + t) * SDIM + k];
    }
    __syncthreads();

    const int j = jb + tid;
    const float bj = b_res[j];
    for (int tg = 0; tg < 64; tg += 4) {
        float a0 = bj, a1 = bj, a2 = bj, a3 = bj;
        #pragma unroll 4
        for (int k = 0; k < 128; k++) {
            float w = Ws[tid * 129 + k];
            a0 = fmaf(w, Us[(tg + 0) * 128 + k], a0);
            a1 = fmaf(w, Us[(tg + 1) * 128 + k], a1);
            a2 = fmaf(w, Us[(tg + 2) * 128 + k], a2);
            a3 = fmaf(w, Us[(tg + 3) * 128 + k], a3);
        }
        g_inproj[(size_t)(tb + tg + 0) * RES + j] = a0;
        g_inproj[(size_t)(tb + tg + 1) * RES + j] = a1;
        g_inproj[(size_t)(tb + tg + 2) * RES + j] = a2;
        g_inproj[(size_t)(tb + tg + 3) * RES + j] = a3;
    }
}

// 4 cols (2 packed half2) of one row against 4 r values.
#define ACC4(Q, RV, A, B)                                                     \
{                                                                             \
    float2 _u;                                                                \
    _u = __half22float2(*(__half2*)&(Q).x);                                   \
    (A) = fmaf(_u.x, (RV).x, (A)); (B) = fmaf(_u.y, (RV).y, (B));             \
    _u = __half22float2(*(__half2*)&(Q).y);                                   \
    (A) = fmaf(_u.x, (RV).z, (A)); (B) = fmaf(_u.y, (RV).w, (B));             \
}

// ---------------------------------------------------------------------------
// Persistent recurrent kernel. Per-block slice = 64 rows x 8192 cols fp16:
//   cols [0,1536)     SMEM-pinned, cols [1536,2560) REGISTER-pinned,
//   cols [2560,8192)  streamed (zigzag across timesteps; L2-resident).
// Pinned/register compute is interleaved INTO the streamed loop so the LTS
// stream never idles behind pure-FMA phases. State arrives via cp.async.cg
// (L2-coherent) overlapped with the deferred output store + inproj prefetch.
// ---------------------------------------------------------------------------
__global__ void __launch_bounds__(THREADS, 1)
esn_kernel(const float* __restrict__ res_state, float* __restrict__ out) {
    extern __shared__ char smraw[];
    float*  r_s  = (float*)smraw;                       // 32 KB state copy
    __half* wpin = (__half*)(smraw + RES * sizeof(float));  // 192 KB pinned W

    const int tid   = threadIdx.x;
    const int rbase = blockIdx.x * RPB;
    const int w     = tid >> 5;
    const int lane  = tid & 31;
    const int lr0   = RPW * w;                     // this warp's first local row
    const int r0g   = rbase + lr0;                 // global first row (mult of 4)

    // Pin SMEM region: cols [0, CPIN) of this block's 64 rows
    for (int idx = tid; idx < RPB * CPIN / 8; idx += THREADS) {
        int r = idx / (CPIN / 8);
        int c = idx % (CPIN / 8);
        *(uint4*)(wpin + r * CPIN + c * 8) =
            *(const uint4*)(g_Wh + (size_t)(rbase + r) * RES + c * 8);
    }

    // Pin REGISTER region: cols [CPIN, CSTR). Lane owns col pair
    // CPIN + 64k + 2*lane, k=0..15, for its 4 rows. 64 uint regs.
    uint32_t wreg[RPW][16];
    #pragma unroll
    for (int j = 0; j < RPW; j++) {
        const __half* src = g_Wh + (size_t)(rbase + lr0 + j) * RES + CPIN + 2 * lane;
        #pragma unroll
        for (int k = 0; k < 16; k++)
            wreg[j][k] = *(const uint32_t*)(src + 64 * k);
    }

    unsigned gen = 0;
    if (tid == 0) gen = *((volatile unsigned*)&g_gen);

    const __half* gw0 = g_Wh + (size_t)(rbase + lr0) * RES;  // row lr0 base
    const __half* sp0 = wpin + lr0 * CPIN;

    float4 ylast = make_float4(0.f, 0.f, 0.f, 0.f);

    for (int t = 0; t < TSTEPS; t++) {
        // Deferred output store for step t-1 (off the critical path)
        if (lane == 0 && t > 0)
            *(float4*)(out + (size_t)(t - 1) * RES + r0g) = ylast;

        // Async state load (L2-direct -> coherent across SMs)
        const float* rsrc = (t == 0) ? res_state : g_rbuf[(t + 1) & 1];
        for (int i = tid; i < RES / 4; i += THREADS)
            cp16(r_s + 4 * i, rsrc + 4 * i);
        asm volatile("cp.async.commit_group;" ::: "memory");

        // Prefetch inproj for this warp's rows (independent of state)
        float4 ipv;
        if (lane == 0)
            ipv = __ldcg((const float4*)(g_inproj + (size_t)t * RES + r0g));

        asm volatile("cp.async.wait_group 0;" ::: "memory");
        __syncthreads();

        float A0 = 0.f, B0 = 0.f, A1 = 0.f, B1 = 0.f;
        float A2 = 0.f, B2 = 0.f, A3 = 0.f, B3 = 0.f;

        #define STREAM_TILE(IT)                                               \
        {                                                                     \
            int c = CSTR + (IT) * 128 + 4 * lane;                             \
            const __half* gp = gw0 + c;                                       \
            uint2 q0 = *(const uint2*)(gp);                                   \
            uint2 q1 = *(const uint2*)(gp + RES);                             \
            uint2 q2 = *(const uint2*)(gp + 2 * RES);                         \
            uint2 q3 = *(const uint2*)(gp + 3 * RES);                         \
            float4 rv = *(const float4*)(r_s + c);                            \
            ACC4(q0, rv, A0, B0); ACC4(q1, rv, A1, B1);                       \
            ACC4(q2, rv, A2, B2); ACC4(q3, rv, A3, B3);                       \
        }
        #define PIN_TILE(IT)                                                  \
        {                                                                     \
            int c = (IT) * 128 + 4 * lane;                                    \
            const __half* sq = sp0 + c;                                       \
            uint2 q0 = *(const uint2*)(sq);                                   \
            uint2 q1 = *(const uint2*)(sq + CPIN);                            \
            uint2 q2 = *(const uint2*)(sq + 2 * CPIN);                        \
            uint2 q3 = *(const uint2*)(sq + 3 * CPIN);                        \
            float4 rv = *(const float4*)(r_s + c);                            \
            ACC4(q0, rv, A0, B0); ACC4(q1, rv, A1, B1);                       \
            ACC4(q2, rv, A2, B2); ACC4(q3, rv, A3, B3);                       \
        }
        #define REG_IT(K)                                                     \
        {                                                                     \
            float2 rr = *(const float2*)(r_s + CPIN + 64 * (K) + 2 * lane);   \
            float2 u;                                                         \
            u = __half22float2(*(__half2*)&wreg[0][(K)]);                     \
            A0 = fmaf(u.x, rr.x, A0); B0 = fmaf(u.y, rr.y, B0);               \
            u = __half22float2(*(__half2*)&wreg[1][(K)]);                     \
            A1 = fmaf(u.x, rr.x, A1); B1 = fmaf(u.y, rr.y, B1);               \
            u = __half22float2(*(__half2*)&wreg[2][(K)]);                     \
            A2 = fmaf(u.x, rr.x, A2); B2 = fmaf(u.y, rr.y, B2);               \
            u = __half22float2(*(__half2*)&wreg[3][(K)]);                     \
            A3 = fmaf(u.x, rr.x, A3); B3 = fmaf(u.y, rr.y, B3);               \
        }

        // Merged loop: streamed tile every iter (zigzag direction), pinned /
        // register tiles interleaved so the fma work rides under the stream.
        if ((t & 1) == 0) {
            #pragma unroll 4
            for (int it = 0; it < NSTRIT; it++) {
                STREAM_TILE(it);
                if (it < NPIN) PIN_TILE(it)
                else if (it < NPIN + 16) REG_IT(it - NPIN)
            }
        } else {
            #pragma unroll 4
            for (int it = 0; it < NSTRIT; it++) {
                STREAM_TILE(NSTRIT - 1 - it);
                if (it < NPIN) PIN_TILE(it)
                else if (it < NPIN + 16) REG_IT(it - NPIN)
            }
        }
        #undef STREAM_TILE
        #undef PIN_TILE
        #undef REG_IT

        float s0 = A0 + B0, s1 = A1 + B1, s2 = A2 + B2, s3 = A3 + B3;
        #pragma unroll
        for (int off = 16; off; off >>= 1) {
            s0 += __shfl_xor_sync(0xffffffffu, s0, off);
            s1 += __shfl_xor_sync(0xffffffffu, s1, off);
            s2 += __shfl_xor_sync(0xffffffffu, s2, off);
            s3 += __shfl_xor_sync(0xffffffffu, s3, off);
        }

        if (lane == 0) {
            float4 y;
            y.x = tanhf(s0 + ipv.x);
            y.y = tanhf(s1 + ipv.y);
            y.z = tanhf(s2 + ipv.z);
            y.w = tanhf(s3 + ipv.w);
            *(float4*)(g_rbuf[t & 1] + r0g) = y;   // state for next step
            ylast = y;                             // out store deferred
            __threadfence();                       // release state write
        }

        // ---- grid-wide barrier (sense via generation counter) ----
        __syncthreads();
        if (tid == 0) {
            gen++;
            unsigned prev = atomicAdd(&g_count, 1u);
            if (prev == NBLK - 1) {
                atomicExch(&g_count, 0u);
                __threadfence();
                *((volatile unsigned*)&g_gen) = gen;
            } else {
                while (*((volatile unsigned*)&g_gen) != gen) { }
            }
            __threadfence();   // acquire
        }
        __syncthreads();
    }

    // Final deferred output store (t = TSTEPS-1)
    if (lane == 0)
        *(float4*)(out + (size_t)(TSTEPS - 1) * RES + r0g) = ylast;
}

// ---------------------------------------------------------------------------
// Inputs (metadata order): in_seq[1024,128], res_state[8192],
//                          W_in[8192,128], W_res[8192,8192], b_res[8192]
// Output: res_seq[1024,8192] float32
// ---------------------------------------------------------------------------
extern "C" void kernel_launch(void* const* d_in, const int* in_sizes, int n_in,
                              void* d_out, int out_size) {
    const float* in_seq    = (const float*)d_in[0];
    const float* res_state = (const float*)d_in[1];
    const float* W_in      = (const float*)d_in[2];
    const float* W_res     = (const float*)d_in[3];
    const float* b_res     = (const float*)d_in[4];
    float* out = (float*)d_out;

    const int inproj_smem = (128 * 129 + 64 * 128) * sizeof(float);  // ~96.5 KB
    const int esn_smem    = RES * sizeof(float) + RPB * CPIN * sizeof(__half); // 224 KB
    cudaFuncSetAttribute(inproj_kernel, cudaFuncAttributeMaxDynamicSharedMemorySize, inproj_smem);
    cudaFuncSetAttribute(esn_kernel,    cudaFuncAttributeMaxDynamicSharedMemorySize, esn_smem);

    // 1) W_res fp32 -> fp16
    {
        size_t n4 = (size_t)RES * RES / 4;
        int threads = 256;
        int blocks  = (int)(n4 / threads);
        convert_kernel<<<blocks, threads>>>(W_res);
    }

    // 2) in_proj = in_seq @ W_in^T + b
    {
        dim3 grid(RES / 128, TSTEPS / 64);
        inproj_kernel<<<grid, 128, inproj_smem>>>(in_seq, W_in, b_res);
    }

    // 3) persistent recurrent rollout
    esn_kernel<<<NBLK, THREADS, esn_smem>>>(res_state, out);
}

// round 13
// speedup vs baseline: 2.0586x; 2.0586x over previous
#include <cuda_runtime.h>
#include <cuda_fp16.h>
#include <math.h>
#include <stdint.h>

// Problem constants
#define RES    8192
#define TSTEPS 1024
#define SDIM   128

// Main kernel config
#define NBLK    128     // persistent blocks, 1 per SM
#define RPB     64      // rows of W_res per block
#define THREADS 512     // 16 warps, 4 rows per warp (128 regs/thread budget)
#define RPW     4       // rows per warp
#define CPIN    1536    // cols pinned in SMEM  (64*1536*2B = 192 KB/SM, 24 MiB chip)
#define CREG    1024    // cols pinned in REGISTERS (64 regs/lane, 16 MiB chip)
#define CSTR    (CPIN + CREG)          // 2560: streamed cols start
#define NSTRIT  ((RES - CSTR) / 128)   // 44 streamed 128-col tiles (88 MiB chip)

// Scratch (static device globals -- no allocations allowed)
__device__ __half  g_Wh[(size_t)RES * RES];            // 128 MiB fp16 weights
__device__ float   g_inproj[(size_t)TSTEPS * RES];     // 32 MiB
__device__ float   g_rbuf[2][RES];                     // double-buffered state
__device__ unsigned g_count;                           // barrier arrivals
__device__ unsigned g_gen;                             // barrier generation

// ---------------------------------------------------------------------------
// fp32 -> fp16 weight conversion
// ---------------------------------------------------------------------------
__global__ void convert_kernel(const float* __restrict__ W) {
    size_t i = ((size_t)blockIdx.x * blockDim.x + threadIdx.x) * 4;
    float4 v = *(const float4*)(W + i);
    __half2* o = (__half2*)(g_Wh + i);
    o[0] = __floats2half2_rn(v.x, v.y);
    o[1] = __floats2half2_rn(v.z, v.w);
}

// ---------------------------------------------------------------------------
// in_proj[t][j] = b[j] + sum_k in_seq[t][k] * W_in[j][k]
// ---------------------------------------------------------------------------
__global__ void inproj_kernel(const float* __restrict__ in_seq,
                              const float* __restrict__ W_in,
                              const float* __restrict__ b_res) {
    extern __shared__ float sm[];
    float* Ws = sm;                 // [128][129] padded
    float* Us = sm + 128 * 129;     // [64][128]
    const int jb  = blockIdx.x * 128;
    const int tb  = blockIdx.y * 64;
    const int tid = threadIdx.x;

    for (int idx = tid; idx < 128 * 128; idx += 128) {
        int r = idx >> 7, k = idx & 127;
        Ws[r * 129 + k] = W_in[(size_t)(jb + r) * SDIM + k];
    }
    for (int idx = tid; idx < 64 * 128; idx += 128) {
        int t = idx >> 7, k = idx & 127;
        Us[idx] = in_seq[(size_t)(tb + t) * SDIM + k];
    }
    __syncthreads();

    const int j = jb + tid;
    const float bj = b_res[j];
    for (int tg = 0; tg < 64; tg += 4) {
        float a0 = bj, a1 = bj, a2 = bj, a3 = bj;
        #pragma unroll 4
        for (int k = 0; k < 128; k++) {
            float w = Ws[tid * 129 + k];
            a0 = fmaf(w, Us[(tg + 0) * 128 + k], a0);
            a1 = fmaf(w, Us[(tg + 1) * 128 + k], a1);
            a2 = fmaf(w, Us[(tg + 2) * 128 + k], a2);
            a3 = fmaf(w, Us[(tg + 3) * 128 + k], a3);
        }
        g_inproj[(size_t)(tb + tg + 0) * RES + j] = a0;
        g_inproj[(size_t)(tb + tg + 1) * RES + j] = a1;
        g_inproj[(size_t)(tb + tg + 2) * RES + j] = a2;
        g_inproj[(size_t)(tb + tg + 3) * RES + j] = a3;
    }
}

// 4 cols (2 packed half2) of one row against 4 r values.
#define ACC4(Q, RV, A, B)                                                     \
{                                                                             \
    float2 _u;                                                                \
    _u = __half22float2(*(__half2*)&(Q).x);                                   \
    (A) = fmaf(_u.x, (RV).x, (A)); (B) = fmaf(_u.y, (RV).y, (B));             \
    _u = __half22float2(*(__half2*)&(Q).y);                                   \
    (A) = fmaf(_u.x, (RV).z, (A)); (B) = fmaf(_u.y, (RV).w, (B));             \
}

// ---------------------------------------------------------------------------
// Persistent recurrent kernel. Per-block slice = 64 rows x 8192 cols fp16:
//   cols [0,1536)     SMEM-pinned  (192 KB/SM, 24 MiB chip)
//   cols [1536,2560)  REGISTER-pinned (64 regs/lane, 16 MiB chip)
//   cols [2560,8192)  streamed, zigzag order across timesteps (88 MiB chip,
//                     L2-resident under LRU with alternating sweep)
// Separate phases (warps drift -> natural cross-warp overlap). inproj is
// prefetched at step start; the out store is deferred one step.
// ---------------------------------------------------------------------------
__global__ void __launch_bounds__(THREADS, 1)
esn_kernel(const float* __restrict__ res_state, float* __restrict__ out) {
    extern __shared__ char smraw[];
    float*  r_s  = (float*)smraw;                       // 32 KB state copy
    __half* wpin = (__half*)(smraw + RES * sizeof(float));  // 192 KB pinned W

    const int tid   = threadIdx.x;
    const int rbase = blockIdx.x * RPB;
    const int w     = tid >> 5;
    const int lane  = tid & 31;
    const int lr0   = RPW * w;                     // this warp's first local row
    const int r0g   = rbase + lr0;                 // global first row (mult of 4)

    // Pin SMEM region: cols [0, CPIN) of this block's 64 rows
    for (int idx = tid; idx < RPB * CPIN / 8; idx += THREADS) {
        int r = idx / (CPIN / 8);
        int c = idx % (CPIN / 8);
        *(uint4*)(wpin + r * CPIN + c * 8) =
            *(const uint4*)(g_Wh + (size_t)(rbase + r) * RES + c * 8);
    }

    // Pin REGISTER region: cols [CPIN, CSTR). Lane owns col pair
    // CPIN + 64k + 2*lane, k=0..15, for its 4 rows. 64 uint regs.
    uint32_t wreg[RPW][16];
    #pragma unroll
    for (int j = 0; j < RPW; j++) {
        const __half* src = g_Wh + (size_t)(rbase + lr0 + j) * RES + CPIN + 2 * lane;
        #pragma unroll
        for (int k = 0; k < 16; k++)
            wreg[j][k] = *(const uint32_t*)(src + 64 * k);
    }

    unsigned gen = 0;
    if (tid == 0) gen = *((volatile unsigned*)&g_gen);

    const __half* gw0 = g_Wh + (size_t)(rbase + lr0) * RES;  // row lr0 base
    const __half* sp0 = wpin + lr0 * CPIN;

    float4 ylast = make_float4(0.f, 0.f, 0.f, 0.f);

    for (int t = 0; t < TSTEPS; t++) {
        // Deferred output store for step t-1 (overlaps other warps' state load)
        if (lane == 0 && t > 0)
            *(float4*)(out + (size_t)(t - 1) * RES + r0g) = ylast;

        // Prefetch inproj for this warp's rows (independent of state)
        float4 ipv;
        if (lane == 0)
            ipv = __ldcg((const float4*)(g_inproj + (size_t)t * RES + r0g));

        // Load current state into SMEM. Cross-SM producer -> must bypass L1.
        const float* rsrc = (t == 0) ? res_state : g_rbuf[(t + 1) & 1];
        for (int i = tid; i < RES / 4; i += THREADS)
            ((float4*)r_s)[i] = __ldcg((const float4*)rsrc + i);
        __syncthreads();

        float A0 = 0.f, B0 = 0.f, A1 = 0.f, B1 = 0.f;
        float A2 = 0.f, B2 = 0.f, A3 = 0.f, B3 = 0.f;

        // -- streamed cols [CSTR, RES), zigzag order across timesteps --
        #define STREAM_TILE(IT)                                               \
        {                                                                     \
            int c = CSTR + (IT) * 128 + 4 * lane;                             \
            const __half* gp = gw0 + c;                                       \
            uint2 q0 = *(const uint2*)(gp);                                   \
            uint2 q1 = *(const uint2*)(gp + RES);                             \
            uint2 q2 = *(const uint2*)(gp + 2 * RES);                         \
            uint2 q3 = *(const uint2*)(gp + 3 * RES);                         \
            float4 rv = *(const float4*)(r_s + c);                            \
            ACC4(q0, rv, A0, B0); ACC4(q1, rv, A1, B1);                       \
            ACC4(q2, rv, A2, B2); ACC4(q3, rv, A3, B3);                       \
        }

        if ((t & 1) == 0) {
            #pragma unroll 4
            for (int it = 0; it < NSTRIT; it++) STREAM_TILE(it);
        } else {
            #pragma unroll 4
            for (int it = NSTRIT - 1; it >= 0; it--) STREAM_TILE(it);
        }
        #undef STREAM_TILE

        // -- SMEM-pinned cols [0, CPIN) --
        #pragma unroll 4
        for (int it = 0; it < CPIN / 128; it++) {
            int c = it * 128 + 4 * lane;
            const __half* sq = sp0 + c;
            uint2 q0 = *(const uint2*)(sq);
            uint2 q1 = *(const uint2*)(sq + CPIN);
            uint2 q2 = *(const uint2*)(sq + 2 * CPIN);
            uint2 q3 = *(const uint2*)(sq + 3 * CPIN);
            float4 rv = *(const float4*)(r_s + c);
            ACC4(q0, rv, A0, B0); ACC4(q1, rv, A1, B1);
            ACC4(q2, rv, A2, B2); ACC4(q3, rv, A3, B3);
        }

        // -- REGISTER-pinned cols [CPIN, CSTR) --
        #pragma unroll
        for (int k = 0; k < 16; k++) {
            float2 rr = *(const float2*)(r_s + CPIN + 64 * k + 2 * lane);
            float2 u;
            u = __half22float2(*(__half2*)&wreg[0][k]);
            A0 = fmaf(u.x, rr.x, A0); B0 = fmaf(u.y, rr.y, B0);
            u = __half22float2(*(__half2*)&wreg[1][k]);
            A1 = fmaf(u.x, rr.x, A1); B1 = fmaf(u.y, rr.y, B1);
            u = __half22float2(*(__half2*)&wreg[2][k]);
            A2 = fmaf(u.x, rr.x, A2); B2 = fmaf(u.y, rr.y, B2);
            u = __half22float2(*(__half2*)&wreg[3][k]);
            A3 = fmaf(u.x, rr.x, A3); B3 = fmaf(u.y, rr.y, B3);
        }

        float s0 = A0 + B0, s1 = A1 + B1, s2 = A2 + B2, s3 = A3 + B3;
        #pragma unroll
        for (int off = 16; off; off >>= 1) {
            s0 += __shfl_xor_sync(0xffffffffu, s0, off);
            s1 += __shfl_xor_sync(0xffffffffu, s1, off);
            s2 += __shfl_xor_sync(0xffffffffu, s2, off);
            s3 += __shfl_xor_sync(0xffffffffu, s3, off);
        }

        if (lane == 0) {
            float4 y;
            y.x = tanhf(s0 + ipv.x);
            y.y = tanhf(s1 + ipv.y);
            y.z = tanhf(s2 + ipv.z);
            y.w = tanhf(s3 + ipv.w);
            *(float4*)(g_rbuf[t & 1] + r0g) = y;   // state for next step
            ylast = y;                             // out store deferred
            __threadfence();                       // release state write
        }

        // ---- grid-wide barrier (sense via generation counter) ----
        __syncthreads();
        if (tid == 0) {
            gen++;
            unsigned prev = atomicAdd(&g_count, 1u);
            if (prev == NBLK - 1) {
                atomicExch(&g_count, 0u);
                __threadfence();
                *((volatile unsigned*)&g_gen) = gen;
            } else {
                while (*((volatile unsigned*)&g_gen) != gen) { __nanosleep(20); }
            }
            __threadfence();   // acquire
        }
        __syncthreads();
    }

    // Final deferred output store (t = TSTEPS-1)
    if (lane == 0)
        *(float4*)(out + (size_t)(TSTEPS - 1) * RES + r0g) = ylast;
}

// ---------------------------------------------------------------------------
// Inputs (metadata order): in_seq[1024,128], res_state[8192],
//                          W_in[8192,128], W_res[8192,8192], b_res[8192]
// Output: res_seq[1024,8192] float32
// ---------------------------------------------------------------------------
extern "C" void kernel_launch(void* const* d_in, const int* in_sizes, int n_in,
                              void* d_out, int out_size) {
    const float* in_seq    = (const float*)d_in[0];
    const float* res_state = (const float*)d_in[1];
    const float* W_in      = (const float*)d_in[2];
    const float* W_res     = (const float*)d_in[3];
    const float* b_res     = (const float*)d_in[4];
    float* out = (float*)d_out;

    const int inproj_smem = (128 * 129 + 64 * 128) * sizeof(float);  // ~96.5 KB
    const int esn_smem    = RES * sizeof(float) + RPB * CPIN * sizeof(__half); // 224 KB
    cudaFuncSetAttribute(inproj_kernel, cudaFuncAttributeMaxDynamicSharedMemorySize, inproj_smem);
    cudaFuncSetAttribute(esn_kernel,    cudaFuncAttributeMaxDynamicSharedMemorySize, esn_smem);

    // 1) W_res fp32 -> fp16
    {
        size_t n4 = (size_t)RES * RES / 4;
        int threads = 256;
        int blocks  = (int)(n4 / threads);
        convert_kernel<<<blocks, threads>>>(W_res);
    }

    // 2) in_proj = in_seq @ W_in^T + b
    {
        dim3 grid(RES / 128, TSTEPS / 64);
        inproj_kernel<<<grid, 128, inproj_smem>>>(in_seq, W_in, b_res);
    }

    // 3) persistent recurrent rollout
    esn_kernel<<<NBLK, THREADS, esn_smem>>>(res_state, out);
}

// round 14
// speedup vs baseline: 2.4733x; 1.2015x over previous
#include <cuda_runtime.h>
#include <cuda_fp16.h>
#include <math.h>
#include <stdint.h>

// Problem constants
#define RES    8192
#define TSTEPS 1024
#define SDIM   128

// Main kernel config
#define NBLK    128     // persistent blocks, 1 per SM
#define RPB     64      // rows of W_res per block
#define THREADS 512     // 16 warps, 4 rows per warp (128 regs/thread budget)
#define RPW     4       // rows per warp
#define CPIN    1536    // cols pinned in SMEM  (64*1536*2B = 192 KB/SM, 24 MiB chip)
#define CREG    1024    // cols pinned in REGISTERS (64 regs/lane, 16 MiB chip)
#define CSTR    (CPIN + CREG)          // 2560: streamed cols start
#define NSTRIT  ((RES - CSTR) / 128)   // 44 streamed 128-col tiles (88 MiB chip)
#define NGRP    4                      // interleave groups
#define SPG     (NSTRIT / NGRP)        // 11 streamed tiles per group
#define PPG     3                      // pinned tiles per group (4*3 = 12)
#define RPG     4                      // register iters per group (4*4 = 16)

// Scratch (static device globals -- no allocations allowed)
__device__ __half  g_Wh[(size_t)RES * RES];            // 128 MiB fp16 weights
__device__ float   g_inproj[(size_t)TSTEPS * RES];     // 32 MiB
__device__ float   g_rbuf[2][RES];                     // double-buffered state
__device__ unsigned g_count;                           // barrier arrivals
__device__ unsigned g_gen;                             // barrier generation

// ---------------------------------------------------------------------------
// fp32 -> fp16 weight conversion
// ---------------------------------------------------------------------------
__global__ void convert_kernel(const float* __restrict__ W) {
    size_t i = ((size_t)blockIdx.x * blockDim.x + threadIdx.x) * 4;
    float4 v = *(const float4*)(W + i);
    __half2* o = (__half2*)(g_Wh + i);
    o[0] = __floats2half2_rn(v.x, v.y);
    o[1] = __floats2half2_rn(v.z, v.w);
}

// ---------------------------------------------------------------------------
// in_proj[t][j] = b[j] + sum_k in_seq[t][k] * W_in[j][k]
// ---------------------------------------------------------------------------
__global__ void inproj_kernel(const float* __restrict__ in_seq,
                              const float* __restrict__ W_in,
                              const float* __restrict__ b_res) {
    extern __shared__ float sm[];
    float* Ws = sm;                 // [128][129] padded
    float* Us = sm + 128 * 129;     // [64][128]
    const int jb  = blockIdx.x * 128;
    const int tb  = blockIdx.y * 64;
    const int tid = threadIdx.x;

    for (int idx = tid; idx < 128 * 128; idx += 128) {
        int r = idx >> 7, k = idx & 127;
        Ws[r * 129 + k] = W_in[(size_t)(jb + r) * SDIM + k];
    }
    for (int idx = tid; idx < 64 * 128; idx += 128) {
        int t = idx >> 7, k = idx & 127;
        Us[idx] = in_seq[(size_t)(tb + t) * SDIM + k];
    }
    __syncthreads();

    const int j = jb + tid;
    const float bj = b_res[j];
    for (int tg = 0; tg < 64; tg += 4) {
        float a0 = bj, a1 = bj, a2 = bj, a3 = bj;
        #pragma unroll 4
        for (int k = 0; k < 128; k++) {
            float w = Ws[tid * 129 + k];
            a0 = fmaf(w, Us[(tg + 0) * 128 + k], a0);
            a1 = fmaf(w, Us[(tg + 1) * 128 + k], a1);
            a2 = fmaf(w, Us[(tg + 2) * 128 + k], a2);
            a3 = fmaf(w, Us[(tg + 3) * 128 + k], a3);
        }
        g_inproj[(size_t)(tb + tg + 0) * RES + j] = a0;
        g_inproj[(size_t)(tb + tg + 1) * RES + j] = a1;
        g_inproj[(size_t)(tb + tg + 2) * RES + j] = a2;
        g_inproj[(size_t)(tb + tg + 3) * RES + j] = a3;
    }
}

// 4 cols (2 packed half2) of one row against 4 r values.
#define ACC4(Q, RV, A, B)                                                     \
{                                                                             \
    float2 _u;                                                                \
    _u = __half22float2(*(__half2*)&(Q).x);                                   \
    (A) = fmaf(_u.x, (RV).x, (A)); (B) = fmaf(_u.y, (RV).y, (B));             \
    _u = __half22float2(*(__half2*)&(Q).y);                                   \
    (A) = fmaf(_u.x, (RV).z, (A)); (B) = fmaf(_u.y, (RV).w, (B));             \
}

// ---------------------------------------------------------------------------
// Persistent recurrent kernel. Per-block slice = 64 rows x 8192 cols fp16:
//   cols [0,1536)     SMEM-pinned  (192 KB/SM, 24 MiB chip)
//   cols [1536,2560)  REGISTER-pinned (64 regs/lane, 16 MiB chip)
//   cols [2560,8192)  streamed, zigzag order across timesteps (88 MiB chip,
//                     L2-resident under LRU with alternating sweep)
// Compute is issued in 4 straight-line groups of (11 streamed tiles, 3 pinned
// tiles, 4 register iters) so pure-FMA bursts never leave the LTS stream idle
// for a whole phase; warps desynchronize across groups. No conditionals in
// the body (the R12 mistake).
// ---------------------------------------------------------------------------
__global__ void __launch_bounds__(THREADS, 1)
esn_kernel(const float* __restrict__ res_state, float* __restrict__ out) {
    extern __shared__ char smraw[];
    float*  r_s  = (float*)smraw;                       // 32 KB state copy
    __half* wpin = (__half*)(smraw + RES * sizeof(float));  // 192 KB pinned W

    const int tid   = threadIdx.x;
    const int rbase = blockIdx.x * RPB;
    const int w     = tid >> 5;
    const int lane  = tid & 31;
    const int lr0   = RPW * w;                     // this warp's first local row
    const int r0g   = rbase + lr0;                 // global first row (mult of 4)

    // Pin SMEM region: cols [0, CPIN) of this block's 64 rows
    for (int idx = tid; idx < RPB * CPIN / 8; idx += THREADS) {
        int r = idx / (CPIN / 8);
        int c = idx % (CPIN / 8);
        *(uint4*)(wpin + r * CPIN + c * 8) =
            *(const uint4*)(g_Wh + (size_t)(rbase + r) * RES + c * 8);
    }

    // Pin REGISTER region: cols [CPIN, CSTR). Lane owns col pair
    // CPIN + 64k + 2*lane, k=0..15, for its 4 rows. 64 uint regs.
    uint32_t wreg[RPW][16];
    #pragma unroll
    for (int j = 0; j < RPW; j++) {
        const __half* src = g_Wh + (size_t)(rbase + lr0 + j) * RES + CPIN + 2 * lane;
        #pragma unroll
        for (int k = 0; k < 16; k++)
            wreg[j][k] = *(const uint32_t*)(src + 64 * k);
    }

    unsigned gen = 0;
    if (tid == 0) gen = *((volatile unsigned*)&g_gen);

    const __half* gw0 = g_Wh + (size_t)(rbase + lr0) * RES;  // row lr0 base
    const __half* sp0 = wpin + lr0 * CPIN;

    for (int t = 0; t < TSTEPS; t++) {
        // Load current state into SMEM. Cross-SM producer -> must bypass L1.
        const float* rsrc = (t == 0) ? res_state : g_rbuf[(t + 1) & 1];
        for (int i = tid; i < RES / 4; i += THREADS)
            ((float4*)r_s)[i] = __ldcg((const float4*)rsrc + i);
        __syncthreads();

        float A0 = 0.f, B0 = 0.f, A1 = 0.f, B1 = 0.f;
        float A2 = 0.f, B2 = 0.f, A3 = 0.f, B3 = 0.f;

        #define STREAM_TILE(IT)                                               \
        {                                                                     \
            int c = CSTR + (IT) * 128 + 4 * lane;                             \
            const __half* gp = gw0 + c;                                       \
            uint2 q0 = *(const uint2*)(gp);                                   \
            uint2 q1 = *(const uint2*)(gp + RES);                             \
            uint2 q2 = *(const uint2*)(gp + 2 * RES);                         \
            uint2 q3 = *(const uint2*)(gp + 3 * RES);                         \
            float4 rv = *(const float4*)(r_s + c);                            \
            ACC4(q0, rv, A0, B0); ACC4(q1, rv, A1, B1);                       \
            ACC4(q2, rv, A2, B2); ACC4(q3, rv, A3, B3);                       \
        }
        #define PIN_TILE(IT)                                                  \
        {                                                                     \
            int c = (IT) * 128 + 4 * lane;                                    \
            const __half* sq = sp0 + c;                                       \
            uint2 q0 = *(const uint2*)(sq);                                   \
            uint2 q1 = *(const uint2*)(sq + CPIN);                            \
            uint2 q2 = *(const uint2*)(sq + 2 * CPIN);                        \
            uint2 q3 = *(const uint2*)(sq + 3 * CPIN);                        \
            float4 rv = *(const float4*)(r_s + c);                            \
            ACC4(q0, rv, A0, B0); ACC4(q1, rv, A1, B1);                       \
            ACC4(q2, rv, A2, B2); ACC4(q3, rv, A3, B3);                       \
        }
        #define REG_IT(K)                                                     \
        {                                                                     \
            float2 rr = *(const float2*)(r_s + CPIN + 64 * (K) + 2 * lane);   \
            float2 u;                                                         \
            u = __half22float2(*(__half2*)&wreg[0][(K)]);                     \
            A0 = fmaf(u.x, rr.x, A0); B0 = fmaf(u.y, rr.y, B0);               \
            u = __half22float2(*(__half2*)&wreg[1][(K)]);                     \
            A1 = fmaf(u.x, rr.x, A1); B1 = fmaf(u.y, rr.y, B1);               \
            u = __half22float2(*(__half2*)&wreg[2][(K)]);                     \
            A2 = fmaf(u.x, rr.x, A2); B2 = fmaf(u.y, rr.y, B2);               \
            u = __half22float2(*(__half2*)&wreg[3][(K)]);                     \
            A3 = fmaf(u.x, rr.x, A3); B3 = fmaf(u.y, rr.y, B3);               \
        }

        // 4 straight-line groups: 11 streamed + 3 pinned + 4 register each.
        if ((t & 1) == 0) {
            #pragma unroll
            for (int grp = 0; grp < NGRP; grp++) {
                #pragma unroll
                for (int j = 0; j < SPG; j++) STREAM_TILE(grp * SPG + j);
                #pragma unroll
                for (int j = 0; j < PPG; j++) PIN_TILE(grp * PPG + j);
                #pragma unroll
                for (int j = 0; j < RPG; j++) REG_IT(grp * RPG + j);
            }
        } else {
            #pragma unroll
            for (int grp = 0; grp < NGRP; grp++) {
                #pragma unroll
                for (int j = 0; j < SPG; j++)
                    STREAM_TILE(NSTRIT - 1 - (grp * SPG + j));
                #pragma unroll
                for (int j = 0; j < PPG; j++) PIN_TILE(grp * PPG + j);
                #pragma unroll
                for (int j = 0; j < RPG; j++) REG_IT(grp * RPG + j);
            }
        }
        #undef STREAM_TILE
        #undef PIN_TILE
        #undef REG_IT

        float s0 = A0 + B0, s1 = A1 + B1, s2 = A2 + B2, s3 = A3 + B3;
        #pragma unroll
        for (int off = 16; off; off >>= 1) {
            s0 += __shfl_xor_sync(0xffffffffu, s0, off);
            s1 += __shfl_xor_sync(0xffffffffu, s1, off);
            s2 += __shfl_xor_sync(0xffffffffu, s2, off);
            s3 += __shfl_xor_sync(0xffffffffu, s3, off);
        }

        if (lane == 0) {
            float4 ipv = *(const float4*)(g_inproj + (size_t)t * RES + r0g);
            float4 y;
            y.x = tanhf(s0 + ipv.x);
            y.y = tanhf(s1 + ipv.y);
            y.z = tanhf(s2 + ipv.z);
            y.w = tanhf(s3 + ipv.w);
            *(float4*)(g_rbuf[t & 1] + r0g) = y;       // state for next step
            *(float4*)(out + (size_t)t * RES + r0g) = y;
            __threadfence();   // release this warp's state writes
        }

        // ---- grid-wide barrier (sense via generation counter) ----
        __syncthreads();
        if (tid == 0) {
            gen++;
            unsigned prev = atomicAdd(&g_count, 1u);
            if (prev == NBLK - 1) {
                atomicExch(&g_count, 0u);
                __threadfence();
                *((volatile unsigned*)&g_gen) = gen;
            } else {
                while (*((volatile unsigned*)&g_gen) != gen) { __nanosleep(20); }
            }
            __threadfence();   // acquire
        }
        __syncthreads();
    }
}

// ---------------------------------------------------------------------------
// Inputs (metadata order): in_seq[1024,128], res_state[8192],
//                          W_in[8192,128], W_res[8192,8192], b_res[8192]
// Output: res_seq[1024,8192] float32
// ---------------------------------------------------------------------------
extern "C" void kernel_launch(void* const* d_in, const int* in_sizes, int n_in,
                              void* d_out, int out_size) {
    const float* in_seq    = (const float*)d_in[0];
    const float* res_state = (const float*)d_in[1];
    const float* W_in      = (const float*)d_in[2];
    const float* W_res     = (const float*)d_in[3];
    const float* b_res     = (const float*)d_in[4];
    float* out = (float*)d_out;

    const int inproj_smem = (128 * 129 + 64 * 128) * sizeof(float);  // ~96.5 KB
    const int esn_smem    = RES * sizeof(float) + RPB * CPIN * sizeof(__half); // 224 KB
    cudaFuncSetAttribute(inproj_kernel, cudaFuncAttributeMaxDynamicSharedMemorySize, inproj_smem);
    cudaFuncSetAttribute(esn_kernel,    cudaFuncAttributeMaxDynamicSharedMemorySize, esn_smem);

    // 1) W_res fp32 -> fp16
    {
        size_t n4 = (size_t)RES * RES / 4;
        int threads = 256;
        int blocks  = (int)(n4 / threads);
        convert_kernel<<<blocks, threads>>>(W_res);
    }

    // 2) in_proj = in_seq @ W_in^T + b
    {
        dim3 grid(RES / 128, TSTEPS / 64);
        inproj_kernel<<<grid, 128, inproj_smem>>>(in_seq, W_in, b_res);
    }

    // 3) persistent recurrent rollout
    esn_kernel<<<NBLK, THREADS, esn_smem>>>(res_state, out);
}